// round 12
// baseline (speedup 1.0000x reference)
#include <cuda_runtime.h>
#include <cuda_bf16.h>
#include <cstdint>

#define Bb 16
#define Nn 4096
#define KS 64
#define Dd 1024
#define Hh 8
#define DHh 128

typedef __nv_bfloat16 bf16;
typedef __nv_bfloat162 bf162;

// ---------------- scratch (device globals) ----------------
__device__ __align__(256) bf16 g_vnh[(size_t)Bb * Nn * Dd];
__device__ __align__(256) bf16 g_vnl[(size_t)Bb * Nn * Dd];
__device__ __align__(256) bf16 g_Wkh[Dd * Dd], g_Wkl[Dd * Dd];
__device__ __align__(256) bf16 g_Wqh[Dd * Dd], g_Wql[Dd * Dd];
__device__ __align__(256) bf16 g_Wvh[Dd * Dd], g_Wvl[Dd * Dd];
__device__ __align__(256) bf16 g_Woh[Dd * Dd], g_Wol[Dd * Dd];
__device__ __align__(256) bf16 g_Wqkh[Dd * Dd], g_Wqkl[Dd * Dd];
__device__ __align__(256) bf16 g_Wvoh[Dd * Dd], g_Wvol[Dd * Dd];
__device__ __align__(256) bf16 g_miwh[3 * Dd * Dd], g_miwl[3 * Dd * Dd];
__device__ __align__(256) bf16 g_mowh[Dd * Dd], g_mowl[Dd * Dd];
__device__ __align__(256) bf16 g_W1h[2 * Dd * Dd], g_W1l[2 * Dd * Dd];
__device__ __align__(256) bf16 g_W2h[2 * Dd * Dd], g_W2l[2 * Dd * Dd];
__device__ __align__(256) bf16 g_snh[Bb * KS * Dd], g_snl[Bb * KS * Dd];
__device__ __align__(256) bf16 g_qh[Bb * KS * Dd], g_ql[Bb * KS * Dd];
__device__ __align__(256) bf16 g_awh[(size_t)Bb * KS * Nn], g_awl[(size_t)Bb * KS * Nn];
__device__ __align__(256) bf16 g_u1h[Bb * KS * Dd], g_u1l[Bb * KS * Dd];
__device__ __align__(256) bf16 g_slbh[Bb * KS * Dd], g_slbl[Bb * KS * Dd];
__device__ __align__(256) bf16 g_sah[Bb * KS * Dd], g_sal[Bb * KS * Dd];
__device__ __align__(256) bf16 g_hh[Bb * KS * Dd], g_hl[Bb * KS * Dd];
__device__ __align__(256) bf16 g_tbh[Bb * KS * 2 * Dd], g_tbl[Bb * KS * 2 * Dd];
__device__ __align__(256) float g_slots[Bb * KS * Dd];
__device__ __align__(256) float g_attn[(size_t)Bb * KS * Nn];
__device__ __align__(256) float g_qkv[Bb * KS * 3 * Dd];
__device__ __align__(256) float g_P[Bb * Hh * KS * KS];
__device__ __align__(256) float g_tmp[Bb * KS * Dd];

__device__ __forceinline__ float gelu_exact(float x) {
    return 0.5f * x * (1.0f + erff(x * 0.7071067811865476f));
}
__device__ __forceinline__ void split1(float v, bf16& h, bf16& l) {
    h = __float2bfloat16(v);
    l = __float2bfloat16(v - __bfloat162float(h));
}

// ---------------- merged weight split ----------------
struct SJ {
    const float* s[8];
    bf16* h[8];
    bf16* l[8];
    int cum[9];
};
__global__ void __launch_bounds__(256) split_all(SJ j) {
    int blk = blockIdx.x;
    int ti = 0;
#pragma unroll
    for (int i = 0; i < 7; i++) ti += (blk >= j.cum[i + 1]) ? 1 : 0;
    int idx = (blk - j.cum[ti]) * 256 + threadIdx.x;
    float4 v = ((const float4*)j.s[ti])[idx];
    bf16 h0, l0, h1, l1, h2, l2, h3, l3;
    split1(v.x, h0, l0); split1(v.y, h1, l1); split1(v.z, h2, l2); split1(v.w, h3, l3);
    ((bf162*)j.h[ti])[2 * idx]     = bf162(h0, h1);
    ((bf162*)j.h[ti])[2 * idx + 1] = bf162(h2, h3);
    ((bf162*)j.l[ti])[2 * idx]     = bf162(l0, l1);
    ((bf162*)j.l[ti])[2 * idx + 1] = bf162(l2, l3);
}

// ---------------- LayerNorm ----------------
__global__ void __launch_bounds__(256) ln_kernel(const float* __restrict__ x,
                                                 const float* __restrict__ res,
                                                 const float* __restrict__ gam,
                                                 const float* __restrict__ bet,
                                                 float* __restrict__ yf,
                                                 bf16* __restrict__ yh,
                                                 bf16* __restrict__ yl) {
    int row = blockIdx.x;
    int tid = threadIdx.x;
    float4 v = ((const float4*)(x + (size_t)row * Dd))[tid];
    if (res) {
        float4 r = ((const float4*)(res + (size_t)row * Dd))[tid];
        v.x += r.x; v.y += r.y; v.z += r.z; v.w += r.w;
    }
    float s  = v.x + v.y + v.z + v.w;
    float ss = v.x * v.x + v.y * v.y + v.z * v.z + v.w * v.w;
#pragma unroll
    for (int o = 16; o > 0; o >>= 1) {
        s  += __shfl_down_sync(0xffffffffu, s, o);
        ss += __shfl_down_sync(0xffffffffu, ss, o);
    }
    __shared__ float wsum[8], wsq[8];
    __shared__ float smean, srstd;
    int w = tid >> 5, l = tid & 31;
    if (l == 0) { wsum[w] = s; wsq[w] = ss; }
    __syncthreads();
    if (tid == 0) {
        float S = 0.f, SS = 0.f;
#pragma unroll
        for (int i = 0; i < 8; i++) { S += wsum[i]; SS += wsq[i]; }
        float mean = S * (1.0f / Dd);
        float var  = SS * (1.0f / Dd) - mean * mean;
        smean = mean;
        srstd = rsqrtf(var + 1e-5f);
    }
    __syncthreads();
    float mean = smean, rstd = srstd;
    float4 gg = ((const float4*)gam)[tid];
    float4 bb = ((const float4*)bet)[tid];
    float4 o;
    o.x = (v.x - mean) * rstd * gg.x + bb.x;
    o.y = (v.y - mean) * rstd * gg.y + bb.y;
    o.z = (v.z - mean) * rstd * gg.z + bb.z;
    o.w = (v.w - mean) * rstd * gg.w + bb.w;
    if (yf) ((float4*)(yf + (size_t)row * Dd))[tid] = o;
    if (yh) {
        bf16 h0, l0, h1, l1, h2, l2, h3, l3;
        split1(o.x, h0, l0); split1(o.y, h1, l1); split1(o.z, h2, l2); split1(o.w, h3, l3);
        bf162* hp = (bf162*)(yh + (size_t)row * Dd);
        bf162* lp = (bf162*)(yl + (size_t)row * Dd);
        hp[2 * tid] = bf162(h0, h1); hp[2 * tid + 1] = bf162(h2, h3);
        lp[2 * tid] = bf162(l0, l1); lp[2 * tid + 1] = bf162(l2, l3);
    }
}

__global__ void __launch_bounds__(256) bcast_slots(const float* __restrict__ si,
                                                   float* __restrict__ slots) {
    int idx = blockIdx.x * 256 + threadIdx.x;
    slots[idx] = si[idx & (KS * Dd - 1)];
}

// ---------------- softmax over SLOT axis ----------------
__global__ void __launch_bounds__(256) softmax_slots(const float* __restrict__ attn,
                                                     bf16* __restrict__ awh,
                                                     bf16* __restrict__ awl) {
    int idx = blockIdx.x * 256 + threadIdx.x;
    int b = idx >> 12;
    int n = idx & (Nn - 1);
    const float* p = attn + (size_t)b * KS * Nn + n;
    float m = -1e30f;
#pragma unroll 8
    for (int k = 0; k < KS; k++) m = fmaxf(m, p[(size_t)k * Nn]);
    float s = 0.f;
#pragma unroll 8
    for (int k = 0; k < KS; k++) s += expf(p[(size_t)k * Nn] - m);
    float inv = 1.0f / s;
    size_t base = (size_t)b * KS * Nn + n;
#pragma unroll 8
    for (int k = 0; k < KS; k++) {
        float e = expf(p[(size_t)k * Nn] - m) * inv;
        bf16 h, l;
        split1(e, h, l);
        awh[base + (size_t)k * Nn] = h;
        awl[base + (size_t)k * Nn] = l;
    }
}

// ---------------- MHA inner ----------------
__global__ void __launch_bounds__(256) mha_scores(const float* __restrict__ qkv,
                                                  float* __restrict__ P) {
    int bh = blockIdx.x;
    int b = bh / Hh, h = bh % Hh;
    const float* base = qkv + (size_t)b * KS * 3 * Dd;
    __shared__ float sk[KS][DHh + 1];
    int tid = threadIdx.x;
    for (int i = tid; i < KS * DHh; i += 256) {
        int kj = i >> 7, dd = i & 127;
        sk[kj][dd] = base[(size_t)kj * 3 * Dd + Dd + h * DHh + dd];
    }
    __syncthreads();
    int w = tid >> 5, lane = tid & 31;
    const float rsDH = 0.08838834764831845f;
    for (int r = 0; r < 8; r++) {
        int qi = w * 8 + r;
        const float* qrow = base + (size_t)qi * 3 * Dd + h * DHh;
        float s0 = 0.f, s1 = 0.f;
#pragma unroll 4
        for (int dd = 0; dd < DHh; dd++) {
            float qd = qrow[dd];
            s0 = fmaf(qd, sk[lane][dd], s0);
            s1 = fmaf(qd, sk[lane + 32][dd], s1);
        }
        s0 *= rsDH; s1 *= rsDH;
        float mx = fmaxf(s0, s1);
#pragma unroll
        for (int o = 16; o > 0; o >>= 1) mx = fmaxf(mx, __shfl_xor_sync(0xffffffffu, mx, o));
        float e0 = expf(s0 - mx), e1 = expf(s1 - mx);
        float sum = e0 + e1;
#pragma unroll
        for (int o = 16; o > 0; o >>= 1) sum += __shfl_xor_sync(0xffffffffu, sum, o);
        float inv = 1.0f / sum;
        P[(size_t)bh * 4096 + qi * 64 + lane]      = e0 * inv;
        P[(size_t)bh * 4096 + qi * 64 + lane + 32] = e1 * inv;
    }
}

__global__ void __launch_bounds__(256) mha_av(const float* __restrict__ qkv,
                                              const float* __restrict__ P,
                                              bf16* __restrict__ sah,
                                              bf16* __restrict__ sal) {
    int bh = blockIdx.x;
    int b = bh / Hh, h = bh % Hh;
    const float* vbase = qkv + (size_t)b * KS * 3 * Dd + 2 * Dd + h * DHh;
    __shared__ float sv[KS][DHh];
    __shared__ float sp[KS][KS];
    int tid = threadIdx.x;
    for (int i = tid; i < KS * DHh; i += 256) {
        int kj = i >> 7, dd = i & 127;
        sv[kj][dd] = vbase[(size_t)kj * 3 * Dd + dd];
    }
    for (int i = tid; i < KS * KS; i += 256)
        sp[i >> 6][i & 63] = P[(size_t)bh * 4096 + i];
    __syncthreads();
    int d = tid & 127;
    int half = tid >> 7;
    for (int j0 = 0; j0 < 32; j0 += 4) {
        int qi = half * 32 + j0;
        float a0 = 0.f, a1 = 0.f, a2 = 0.f, a3 = 0.f;
#pragma unroll 8
        for (int kj = 0; kj < KS; kj++) {
            float vv = sv[kj][d];
            a0 = fmaf(sp[qi][kj],     vv, a0);
            a1 = fmaf(sp[qi + 1][kj], vv, a1);
            a2 = fmaf(sp[qi + 2][kj], vv, a2);
            a3 = fmaf(sp[qi + 3][kj], vv, a3);
        }
        size_t o = (size_t)b * KS * Dd + (size_t)qi * Dd + h * DHh + d;
        bf16 h0, l0;
        split1(a0, h0, l0); sah[o] = h0;          sal[o] = l0;
        split1(a1, h0, l0); sah[o + Dd] = h0;     sal[o + Dd] = l0;
        split1(a2, h0, l0); sah[o + 2 * Dd] = h0; sal[o + 2 * Dd] = l0;
        split1(a3, h0, l0); sah[o + 3 * Dd] = h0; sal[o + 3 * Dd] = l0;
    }
}

// ================= split-bf16 GEMM v5: BM=64, BK=32, 3-stage, 128 threads =================
// gemmx<TB, BN>: BN in {32,64,128}. Warp grid 2x2, warp tile 32 x (BN/2).
// 3-stage cp.async ring, 1 barrier per 32-K tile. Overwrite-safe: tile t+2 is
// issued into the stage consumed at t-1 (all threads past it via tile-t barrier).

__device__ __forceinline__ void mma_bf16(float* d, const uint32_t* a, uint32_t b0, uint32_t b1) {
    asm volatile(
        "mma.sync.aligned.m16n8k16.row.col.f32.bf16.bf16.f32 "
        "{%0,%1,%2,%3}, {%4,%5,%6,%7}, {%8,%9}, {%0,%1,%2,%3};\n"
        : "+f"(d[0]), "+f"(d[1]), "+f"(d[2]), "+f"(d[3])
        : "r"(a[0]), "r"(a[1]), "r"(a[2]), "r"(a[3]), "r"(b0), "r"(b1));
}
__device__ __forceinline__ void cp16(bf16* s, const bf16* g) {
    uint32_t sa = (uint32_t)__cvta_generic_to_shared(s);
    asm volatile("cp.async.cg.shared.global [%0], [%1], 16;\n" :: "r"(sa), "l"(g));
}
#define LDSM4(r0, r1, r2, r3, a) \
    asm volatile("ldmatrix.sync.aligned.m8n8.x4.shared.b16 {%0,%1,%2,%3}, [%4];\n" \
                 : "=r"(r0), "=r"(r1), "=r"(r2), "=r"(r3) : "r"(a))
#define LDSM4T(r0, r1, r2, r3, a) \
    asm volatile("ldmatrix.sync.aligned.m8n8.x4.trans.shared.b16 {%0,%1,%2,%3}, [%4];\n" \
                 : "=r"(r0), "=r"(r1), "=r"(r2), "=r"(r3) : "r"(a))

template <bool TB, int BN>
__global__ void __launch_bounds__(128) gemmx(
    const bf16* __restrict__ Ah, const bf16* __restrict__ Al,
    const bf16* __restrict__ Bh, const bf16* __restrict__ Bl,
    int Kd, int ldb, long long sA, long long sB, float alpha,
    float* __restrict__ Cf, int ldc, long long sC,
    bf16* __restrict__ Ch, bf16* __restrict__ Cl, int ldch, long long sCh,
    const float* __restrict__ bias,
    const float* __restrict__ add, int ldadd, long long sAdd, int act) {
    constexpr int NPW = BN / 2;
    constexpr int PP  = (NPW + 15) / 16;
    constexpr int NS  = NPW / 8;
    constexpr int AOFL = 64 * 40;            // A-lo offset (bf16 units)
    constexpr int BOF  = 2 * 64 * 40;        // 5120, B region offset
    constexpr int BROW = TB ? 40 : (BN + 8);
    constexpr int BSZH = TB ? BN * 40 : 32 * (BN + 8);
    constexpr int STG = BOF + 2 * BSZH;      // bf16 units per stage
    extern __shared__ __align__(16) bf16 smg[];

    int bz = blockIdx.z;
    Ah += bz * sA; Al += bz * sA;
    Bh += bz * sB; Bl += bz * sB;
    if (Cf) Cf += bz * sC;
    if (Ch) { Ch += bz * sCh; Cl += bz * sCh; }
    if (add) add += bz * sAdd;

    int bm = blockIdx.y * 64;
    int bn = blockIdx.x * BN;
    int tid = threadIdx.x, lane = tid & 31, wid = tid >> 5;
    int wm = (wid >> 1) * 32;
    int wn = (wid & 1) * NPW;
    int r = lane >> 2, cc = lane & 3;
    int arow = lane & 15, ahalf = lane >> 4;

    float acc[2][NS][4] = {};
    uint32_t ah[2][4], al[2][4], bh[NS][2], bl[NS][2];
    uint32_t base = 0;

    auto load_tile = [&](int st, int k0) {
        bf16* s = smg + st * STG;
        {
            int c = tid, c2 = tid + 128;
            int row = c >> 2, kq = c & 3;
            int row2 = c2 >> 2, kq2 = c2 & 3;
            cp16(s + row * 40 + kq * 8,          Ah + (size_t)(bm + row) * Kd + k0 + kq * 8);
            cp16(s + row2 * 40 + kq2 * 8,        Ah + (size_t)(bm + row2) * Kd + k0 + kq2 * 8);
            cp16(s + AOFL + row * 40 + kq * 8,   Al + (size_t)(bm + row) * Kd + k0 + kq * 8);
            cp16(s + AOFL + row2 * 40 + kq2 * 8, Al + (size_t)(bm + row2) * Kd + k0 + kq2 * 8);
        }
        if (TB) {
#pragma unroll
            for (int c = tid; c < BN * 4; c += 128) {
                int row = c >> 2, kq = c & 3;
                cp16(s + BOF + row * 40 + kq * 8,        Bh + (size_t)(bn + row) * ldb + k0 + kq * 8);
                cp16(s + BOF + BSZH + row * 40 + kq * 8, Bl + (size_t)(bn + row) * ldb + k0 + kq * 8);
            }
        } else {
            constexpr int CH = BN / 8;
#pragma unroll
            for (int c = tid; c < 32 * CH; c += 128) {
                int row = c / CH, ch = c % CH;
                cp16(s + BOF + row * BROW + ch * 8,        Bh + (size_t)(k0 + row) * ldb + bn + ch * 8);
                cp16(s + BOF + BSZH + row * BROW + ch * 8, Bl + (size_t)(k0 + row) * ldb + bn + ch * 8);
            }
        }
        asm volatile("cp.async.commit_group;\n");
    };

    auto load_frags = [&](int s) {
#pragma unroll
        for (int ms = 0; ms < 2; ms++) {
            uint32_t ad = base + ((wm + ms * 16 + arow) * 40 + s * 16 + ahalf * 8) * 2;
            LDSM4(ah[ms][0], ah[ms][1], ah[ms][2], ah[ms][3], ad);
            LDSM4(al[ms][0], al[ms][1], al[ms][2], al[ms][3], ad + AOFL * 2);
        }
        if (TB) {
#pragma unroll
            for (int pp = 0; pp < PP; pp++) {
                uint32_t bd = base + (BOF + (wn + pp * 16 + arow) * 40 + s * 16 + ahalf * 8) * 2;
                uint32_t r0, r1, r2, r3;
                LDSM4(r0, r1, r2, r3, bd);
                bh[2 * pp][0] = r0; bh[2 * pp + 1][0] = r1;
                bh[2 * pp][1] = r2; bh[2 * pp + 1][1] = r3;
                LDSM4(r0, r1, r2, r3, bd + BSZH * 2);
                bl[2 * pp][0] = r0; bl[2 * pp + 1][0] = r1;
                bl[2 * pp][1] = r2; bl[2 * pp + 1][1] = r3;
            }
        } else {
#pragma unroll
            for (int pp = 0; pp < PP; pp++) {
                uint32_t bd = base + (BOF + (s * 16 + arow) * BROW + wn + pp * 16 + ahalf * 8) * 2;
                uint32_t r0, r1, r2, r3;
                LDSM4T(r0, r1, r2, r3, bd);
                bh[2 * pp][0] = r0; bh[2 * pp][1] = r1;
                bh[2 * pp + 1][0] = r2; bh[2 * pp + 1][1] = r3;
                LDSM4T(r0, r1, r2, r3, bd + BSZH * 2);
                bl[2 * pp][0] = r0; bl[2 * pp][1] = r1;
                bl[2 * pp + 1][0] = r2; bl[2 * pp + 1][1] = r3;
            }
        }
    };

    auto mma_all = [&]() {
#pragma unroll
        for (int ns = 0; ns < NS; ns++)
#pragma unroll
            for (int ms = 0; ms < 2; ms++)
                mma_bf16(acc[ms][ns], ah[ms], bh[ns][0], bh[ns][1]);
#pragma unroll
        for (int ns = 0; ns < NS; ns++)
#pragma unroll
            for (int ms = 0; ms < 2; ms++)
                mma_bf16(acc[ms][ns], ah[ms], bl[ns][0], bl[ns][1]);
#pragma unroll
        for (int ns = 0; ns < NS; ns++)
#pragma unroll
            for (int ms = 0; ms < 2; ms++)
                mma_bf16(acc[ms][ns], al[ms], bh[ns][0], bh[ns][1]);
    };

    int T = Kd / 32;
    load_tile(0, 0);
    load_tile(1, 32);
    uint32_t smem_base = (uint32_t)__cvta_generic_to_shared(smg);

    for (int t = 0; t < T; t++) {
        if (t + 1 < T) asm volatile("cp.async.wait_group 1;\n");
        else           asm volatile("cp.async.wait_group 0;\n");
        __syncthreads();
        if (t + 2 < T) {
            int st = t + 2; st -= (st / 3) * 3;
            load_tile(st, (t + 2) * 32);
        }
        int cst = t - (t / 3) * 3;
        base = smem_base + cst * STG * 2;
        load_frags(0);
        mma_all();
        load_frags(1);
        mma_all();
    }

    // epilogue
#pragma unroll
    for (int ms = 0; ms < 2; ms++) {
        int i0 = bm + wm + ms * 16 + r;
#pragma unroll
        for (int ns = 0; ns < NS; ns++) {
            int j = bn + wn + ns * 8 + 2 * cc;
            float v00 = acc[ms][ns][0] * alpha, v01 = acc[ms][ns][1] * alpha;
            float v10 = acc[ms][ns][2] * alpha, v11 = acc[ms][ns][3] * alpha;
            if (bias) {
                float bj0 = bias[j], bj1 = bias[j + 1];
                v00 += bj0; v01 += bj1; v10 += bj0; v11 += bj1;
            }
            if (act == 1) {
                v00 = gelu_exact(v00); v01 = gelu_exact(v01);
                v10 = gelu_exact(v10); v11 = gelu_exact(v11);
            }
            if (add) {
                v00 += add[(size_t)i0 * ldadd + j];
                v01 += add[(size_t)i0 * ldadd + j + 1];
                v10 += add[(size_t)(i0 + 8) * ldadd + j];
                v11 += add[(size_t)(i0 + 8) * ldadd + j + 1];
            }
            if (Cf) {
                float2 a2; a2.x = v00; a2.y = v01;
                float2 b2; b2.x = v10; b2.y = v11;
                *(float2*)(Cf + (size_t)i0 * ldc + j) = a2;
                *(float2*)(Cf + (size_t)(i0 + 8) * ldc + j) = b2;
            }
            if (Ch) {
                bf16 h00, l00, h01, l01, h10, l10, h11, l11;
                split1(v00, h00, l00); split1(v01, h01, l01);
                split1(v10, h10, l10); split1(v11, h11, l11);
                *(bf162*)(Ch + (size_t)i0 * ldch + j) = bf162(h00, h01);
                *(bf162*)(Cl + (size_t)i0 * ldch + j) = bf162(l00, l01);
                *(bf162*)(Ch + (size_t)(i0 + 8) * ldch + j) = bf162(h10, h11);
                *(bf162*)(Cl + (size_t)(i0 + 8) * ldch + j) = bf162(l10, l11);
            }
        }
    }
}

// ---------------- launcher ----------------
#define SYM(p, s) cudaGetSymbolAddress((void**)&p, s)

extern "C" void kernel_launch(void* const* d_in, const int* in_sizes, int n_in,
                              void* d_out, int out_size) {
    const float* vis       = (const float*)d_in[0];
    const float* slot_init = (const float*)d_in[1];
    const float* ln_vis_g  = (const float*)d_in[2];
    const float* ln_vis_b  = (const float*)d_in[3];
    const float* ln_sl_g   = (const float*)d_in[4];
    const float* ln_sl_b   = (const float*)d_in[5];
    const float* Wq        = (const float*)d_in[6];
    const float* Wk        = (const float*)d_in[7];
    const float* Wv        = (const float*)d_in[8];
    const float* Wo        = (const float*)d_in[9];
    const float* mha_in_w  = (const float*)d_in[10];
    const float* mha_in_b  = (const float*)d_in[11];
    const float* mha_out_w = (const float*)d_in[12];
    const float* mha_out_b = (const float*)d_in[13];
    const float* ln_sa_g   = (const float*)d_in[14];
    const float* ln_sa_b   = (const float*)d_in[15];
    const float* ln_ffn_g  = (const float*)d_in[16];
    const float* ln_ffn_b  = (const float*)d_in[17];
    const float* W1        = (const float*)d_in[18];
    const float* b1        = (const float*)d_in[19];
    const float* W2        = (const float*)d_in[20];
    const float* b2        = (const float*)d_in[21];

    bf16 *vnh, *vnl, *Wkh, *Wkl, *Wqh, *Wql, *Wvh, *Wvl, *Woh, *Wol;
    bf16 *Wqkh, *Wqkl, *Wvoh, *Wvol, *miwh, *miwl, *mowh, *mowl;
    bf16 *W1h, *W1l, *W2h, *W2l, *snh, *snl, *qh, *ql, *awh, *awl;
    bf16 *u1h, *u1l, *slbh, *slbl, *sah, *sal, *hh, *hl, *tbh, *tbl;
    float *slots, *attn, *qkv, *P, *tmp;
    SYM(vnh, g_vnh); SYM(vnl, g_vnl);
    SYM(Wkh, g_Wkh); SYM(Wkl, g_Wkl); SYM(Wqh, g_Wqh); SYM(Wql, g_Wql);
    SYM(Wvh, g_Wvh); SYM(Wvl, g_Wvl); SYM(Woh, g_Woh); SYM(Wol, g_Wol);
    SYM(Wqkh, g_Wqkh); SYM(Wqkl, g_Wqkl); SYM(Wvoh, g_Wvoh); SYM(Wvol, g_Wvol);
    SYM(miwh, g_miwh); SYM(miwl, g_miwl); SYM(mowh, g_mowh); SYM(mowl, g_mowl);
    SYM(W1h, g_W1h); SYM(W1l, g_W1l); SYM(W2h, g_W2h); SYM(W2l, g_W2l);
    SYM(snh, g_snh); SYM(snl, g_snl); SYM(qh, g_qh); SYM(ql, g_ql);
    SYM(awh, g_awh); SYM(awl, g_awl); SYM(u1h, g_u1h); SYM(u1l, g_u1l);
    SYM(slbh, g_slbh); SYM(slbl, g_slbl); SYM(sah, g_sah); SYM(sal, g_sal);
    SYM(hh, g_hh); SYM(hl, g_hl); SYM(tbh, g_tbh); SYM(tbl, g_tbl);
    SYM(slots, g_slots); SYM(attn, g_attn); SYM(qkv, g_qkv); SYM(P, g_P); SYM(tmp, g_tmp);

    float* out = (float*)d_out;

    // smem bytes = STG(bf16) * 3 stages * 2B
    const int SM_NT32  = (5120 + 2 * 32 * 40) * 3 * 2;    // 46080
    const int SM_NN32  = (5120 + 2 * 32 * 40) * 3 * 2;    // 46080
    const int SM_NT128 = (5120 + 2 * 128 * 40) * 3 * 2;   // 92160
    const int SM_NN64  = (5120 + 2 * 32 * 72) * 3 * 2;    // 58368
    cudaFuncSetAttribute(gemmx<true, 32>,  cudaFuncAttributeMaxDynamicSharedMemorySize, SM_NT32);
    cudaFuncSetAttribute(gemmx<false, 32>, cudaFuncAttributeMaxDynamicSharedMemorySize, SM_NN32);
    cudaFuncSetAttribute(gemmx<true, 128>, cudaFuncAttributeMaxDynamicSharedMemorySize, SM_NT128);
    cudaFuncSetAttribute(gemmx<false, 64>, cudaFuncAttributeMaxDynamicSharedMemorySize, SM_NN64);

    // ---- merged weight split ----
    {
        SJ j;
        j.s[0] = Wq;  j.h[0] = Wqh;  j.l[0] = Wql;
        j.s[1] = Wk;  j.h[1] = Wkh;  j.l[1] = Wkl;
        j.s[2] = Wv;  j.h[2] = Wvh;  j.l[2] = Wvl;
        j.s[3] = Wo;  j.h[3] = Woh;  j.l[3] = Wol;
        j.s[4] = mha_out_w; j.h[4] = mowh; j.l[4] = mowl;
        j.s[5] = mha_in_w;  j.h[5] = miwh; j.l[5] = miwl;
        j.s[6] = W1;  j.h[6] = W1h;  j.l[6] = W1l;
        j.s[7] = W2;  j.h[7] = W2h;  j.l[7] = W2l;
        int blocks[8] = {1024, 1024, 1024, 1024, 1024, 3072, 2048, 2048};
        j.cum[0] = 0;
        for (int i = 0; i < 8; i++) j.cum[i + 1] = j.cum[i] + blocks[i];
        split_all<<<j.cum[8], 256>>>(j);
    }

    // vn = LN(visual_tokens) -> split bf16
    ln_kernel<<<Bb * Nn, 256>>>(vis, nullptr, ln_vis_g, ln_vis_b, nullptr, vnh, vnl);

    // Wqk = Wq @ Wk^T (NT); Wvo = Wv @ Wo (NN)
    gemmx<true, 32><<<dim3(32, 16, 1), 128, SM_NT32>>>(Wqh, Wql, Wkh, Wkl, Dd, Dd, 0, 0, 1.0f,
        nullptr, 0, 0, Wqkh, Wqkl, Dd, 0, nullptr, nullptr, 0, 0, 0);
    gemmx<false, 32><<<dim3(32, 16, 1), 128, SM_NN32>>>(Wvh, Wvl, Woh, Wol, Dd, Dd, 0, 0, 1.0f,
        nullptr, 0, 0, Wvoh, Wvol, Dd, 0, nullptr, nullptr, 0, 0, 0);

    bcast_slots<<<(Bb * KS * Dd) / 256, 256>>>(slot_init, slots);

    const int Mfull = Bb * KS;  // 1024
    for (int it = 0; it < 2; it++) {
        ln_kernel<<<Mfull, 256>>>(slots, nullptr, ln_sl_g, ln_sl_b, nullptr, snh, snl);
        // q = sn @ Wqk  (NN)
        gemmx<false, 32><<<dim3(32, 16, 1), 128, SM_NN32>>>(snh, snl, Wqkh, Wqkl, Dd, Dd, 0, 0, 1.0f,
            nullptr, 0, 0, qh, ql, Dd, 0, nullptr, nullptr, 0, 0, 0);
        // attn[b] = (1/32) q[b] @ vn[b]^T  (NT, M=64, N=4096)
        gemmx<true, 128><<<dim3(32, 1, Bb), 128, SM_NT128>>>(qh, ql, vnh, vnl, Dd, Dd,
            (long long)KS * Dd, (long long)Nn * Dd, 0.03125f,
            attn, Nn, (long long)KS * Nn, nullptr, nullptr, 0, 0,
            nullptr, nullptr, 0, 0, 0);
        softmax_slots<<<(Bb * Nn) / 256, 256>>>(attn, awh, awl);
        // u1[b] = aw[b] @ vn[b]  (NN, M=64, K=4096)
        gemmx<false, 64><<<dim3(16, 1, Bb), 128, SM_NN64>>>(awh, awl, vnh, vnl, Nn, Dd,
            (long long)KS * Nn, (long long)Nn * Dd, 1.0f,
            nullptr, 0, 0, u1h, u1l, Dd, (long long)KS * Dd,
            nullptr, nullptr, 0, 0, 0);
        // slots = slots + u1 @ Wvo  (NN)
        gemmx<false, 32><<<dim3(32, 16, 1), 128, SM_NN32>>>(u1h, u1l, Wvoh, Wvol, Dd, Dd, 0, 0, 1.0f,
            slots, Dd, 0, slbh, slbl, Dd, 0, nullptr, slots, Dd, 0, 0);
        // qkv = slots @ mha_in_w^T + b  (NT, N=3072)
        gemmx<true, 32><<<dim3(96, 16, 1), 128, SM_NT32>>>(slbh, slbl, miwh, miwl, Dd, Dd, 0, 0, 1.0f,
            qkv, 3 * Dd, 0, nullptr, nullptr, 0, 0, mha_in_b, nullptr, 0, 0, 0);
        mha_scores<<<Bb * Hh, 256>>>(qkv, P);
        mha_av<<<Bb * Hh, 256>>>(qkv, P, sah, sal);
        // tmp = sa @ mha_out_w^T + b  (NT)
        gemmx<true, 32><<<dim3(32, 16, 1), 128, SM_NT32>>>(sah, sal, mowh, mowl, Dd, Dd, 0, 0, 1.0f,
            tmp, Dd, 0, nullptr, nullptr, 0, 0, mha_out_b, nullptr, 0, 0, 0);
        ln_kernel<<<Mfull, 256>>>(slots, tmp, ln_sa_g, ln_sa_b, slots, nullptr, nullptr);
    }

    ln_kernel<<<Mfull, 256>>>(slots, nullptr, ln_ffn_g, ln_ffn_b, nullptr, hh, hl);
    // tb = gelu(h @ W1 + b1)  (NN, N=2048)
    gemmx<false, 32><<<dim3(64, 16, 1), 128, SM_NN32>>>(hh, hl, W1h, W1l, Dd, 2 * Dd, 0, 0, 1.0f,
        nullptr, 0, 0, tbh, tbl, 2 * Dd, 0, b1, nullptr, 0, 0, 1);
    // out = slots + tb @ W2 + b2  (NN, K=2048)
    gemmx<false, 32><<<dim3(32, 16, 1), 128, SM_NN32>>>(tbh, tbl, W2h, W2l, 2 * Dd, Dd, 0, 0, 1.0f,
        out, Dd, 0, nullptr, nullptr, 0, 0, b2, slots, Dd, 0, 0);
}

// round 14
// speedup vs baseline: 1.1463x; 1.1463x over previous
#include <cuda_runtime.h>
#include <cuda_bf16.h>
#include <cuda_fp16.h>
#include <cstdint>

#define Bb 16
#define Nn 4096
#define KS 64
#define Dd 1024
#define Hh 8
#define DHh 128

// NOTE: "bf16" name kept to minimize churn; payload is fp16 (better split accuracy).
typedef __half bf16;
typedef __half2 bf162;
__device__ __forceinline__ bf162 mk2(bf16 a, bf16 b) { return __halves2half2(a, b); }

// ---------------- scratch (device globals) ----------------
__device__ __align__(256) bf16 g_vnh[(size_t)Bb * Nn * Dd];
__device__ __align__(256) bf16 g_vnl[(size_t)Bb * Nn * Dd];
__device__ __align__(256) bf16 g_Wkh[Dd * Dd], g_Wkl[Dd * Dd];
__device__ __align__(256) bf16 g_Wqh[Dd * Dd], g_Wql[Dd * Dd];
__device__ __align__(256) bf16 g_Wvh[Dd * Dd], g_Wvl[Dd * Dd];
__device__ __align__(256) bf16 g_Woh[Dd * Dd], g_Wol[Dd * Dd];
__device__ __align__(256) bf16 g_Wqkh[Dd * Dd], g_Wqkl[Dd * Dd];
__device__ __align__(256) bf16 g_Wvoh[Dd * Dd], g_Wvol[Dd * Dd];
__device__ __align__(256) bf16 g_miwh[3 * Dd * Dd], g_miwl[3 * Dd * Dd];
__device__ __align__(256) bf16 g_mowh[Dd * Dd], g_mowl[Dd * Dd];
__device__ __align__(256) bf16 g_W1h[2 * Dd * Dd], g_W1l[2 * Dd * Dd];
__device__ __align__(256) bf16 g_W2h[2 * Dd * Dd], g_W2l[2 * Dd * Dd];
__device__ __align__(256) bf16 g_snh[Bb * KS * Dd], g_snl[Bb * KS * Dd];
__device__ __align__(256) bf16 g_qh[Bb * KS * Dd], g_ql[Bb * KS * Dd];
__device__ __align__(256) bf16 g_awh[(size_t)Bb * KS * Nn], g_awl[(size_t)Bb * KS * Nn];
__device__ __align__(256) bf16 g_u1h[Bb * KS * Dd], g_u1l[Bb * KS * Dd];
__device__ __align__(256) bf16 g_slbh[Bb * KS * Dd], g_slbl[Bb * KS * Dd];
__device__ __align__(256) bf16 g_sah[Bb * KS * Dd], g_sal[Bb * KS * Dd];
__device__ __align__(256) bf16 g_hh[Bb * KS * Dd], g_hl[Bb * KS * Dd];
__device__ __align__(256) bf16 g_tbh[Bb * KS * 2 * Dd], g_tbl[Bb * KS * 2 * Dd];
__device__ __align__(256) float g_slots[Bb * KS * Dd];
__device__ __align__(256) float g_qkv[Bb * KS * 3 * Dd];
__device__ __align__(256) float g_tmp[Bb * KS * Dd];

__device__ __forceinline__ float gelu_exact(float x) {
    return 0.5f * x * (1.0f + erff(x * 0.7071067811865476f));
}
__device__ __forceinline__ void split1(float v, bf16& h, bf16& l) {
    h = __float2half_rn(v);
    l = __float2half_rn(v - __half2float(h));
}

// ---------------- merged weight split ----------------
struct SJ {
    const float* s[8];
    bf16* h[8];
    bf16* l[8];
    int cum[9];
};
__global__ void __launch_bounds__(256) split_all(SJ j) {
    int blk = blockIdx.x;
    int ti = 0;
#pragma unroll
    for (int i = 0; i < 7; i++) ti += (blk >= j.cum[i + 1]) ? 1 : 0;
    int idx = (blk - j.cum[ti]) * 256 + threadIdx.x;
    float4 v = ((const float4*)j.s[ti])[idx];
    bf16 h0, l0, h1, l1, h2, l2, h3, l3;
    split1(v.x, h0, l0); split1(v.y, h1, l1); split1(v.z, h2, l2); split1(v.w, h3, l3);
    ((bf162*)j.h[ti])[2 * idx]     = mk2(h0, h1);
    ((bf162*)j.h[ti])[2 * idx + 1] = mk2(h2, h3);
    ((bf162*)j.l[ti])[2 * idx]     = mk2(l0, l1);
    ((bf162*)j.l[ti])[2 * idx + 1] = mk2(l2, l3);
}

// ---------------- LayerNorm ----------------
__global__ void __launch_bounds__(256) ln_kernel(const float* __restrict__ x,
                                                 const float* __restrict__ res,
                                                 const float* __restrict__ gam,
                                                 const float* __restrict__ bet,
                                                 float* __restrict__ yf,
                                                 bf16* __restrict__ yh,
                                                 bf16* __restrict__ yl) {
    int row = blockIdx.x;
    int tid = threadIdx.x;
    float4 v = ((const float4*)(x + (size_t)row * Dd))[tid];
    if (res) {
        float4 r = ((const float4*)(res + (size_t)row * Dd))[tid];
        v.x += r.x; v.y += r.y; v.z += r.z; v.w += r.w;
    }
    float s  = v.x + v.y + v.z + v.w;
    float ss = v.x * v.x + v.y * v.y + v.z * v.z + v.w * v.w;
#pragma unroll
    for (int o = 16; o > 0; o >>= 1) {
        s  += __shfl_down_sync(0xffffffffu, s, o);
        ss += __shfl_down_sync(0xffffffffu, ss, o);
    }
    __shared__ float wsum[8], wsq[8];
    __shared__ float smean, srstd;
    int w = tid >> 5, l = tid & 31;
    if (l == 0) { wsum[w] = s; wsq[w] = ss; }
    __syncthreads();
    if (tid == 0) {
        float S = 0.f, SS = 0.f;
#pragma unroll
        for (int i = 0; i < 8; i++) { S += wsum[i]; SS += wsq[i]; }
        float mean = S * (1.0f / Dd);
        float var  = SS * (1.0f / Dd) - mean * mean;
        smean = mean;
        srstd = rsqrtf(var + 1e-5f);
    }
    __syncthreads();
    float mean = smean, rstd = srstd;
    float4 gg = ((const float4*)gam)[tid];
    float4 bb = ((const float4*)bet)[tid];
    float4 o;
    o.x = (v.x - mean) * rstd * gg.x + bb.x;
    o.y = (v.y - mean) * rstd * gg.y + bb.y;
    o.z = (v.z - mean) * rstd * gg.z + bb.z;
    o.w = (v.w - mean) * rstd * gg.w + bb.w;
    if (yf) ((float4*)(yf + (size_t)row * Dd))[tid] = o;
    if (yh) {
        bf16 h0, l0, h1, l1, h2, l2, h3, l3;
        split1(o.x, h0, l0); split1(o.y, h1, l1); split1(o.z, h2, l2); split1(o.w, h3, l3);
        bf162* hp = (bf162*)(yh + (size_t)row * Dd);
        bf162* lp = (bf162*)(yl + (size_t)row * Dd);
        hp[2 * tid] = mk2(h0, h1); hp[2 * tid + 1] = mk2(h2, h3);
        lp[2 * tid] = mk2(l0, l1); lp[2 * tid + 1] = mk2(l2, l3);
    }
}

__global__ void __launch_bounds__(256) bcast_slots(const float* __restrict__ si,
                                                   float* __restrict__ slots) {
    int idx = blockIdx.x * 256 + threadIdx.x;
    slots[idx] = si[idx & (KS * Dd - 1)];
}

// ---------------- fused MHA inner: scores + softmax + AV in one kernel ----------------
__global__ void __launch_bounds__(256) mha_fused(const float* __restrict__ qkv,
                                                 bf16* __restrict__ sah,
                                                 bf16* __restrict__ sal) {
    extern __shared__ char smc[];
    float (*sk)[DHh + 1] = (float(*)[DHh + 1])smc;                    // 33024 B
    float (*sv)[DHh]     = (float(*)[DHh])(smc + 33024);              // 32768 B
    float (*sp)[KS]      = (float(*)[KS])(smc + 65792);               // 16384 B
    int bh = blockIdx.x;
    int b = bh / Hh, h = bh % Hh;
    const float* base = qkv + (size_t)b * KS * 3 * Dd;
    int tid = threadIdx.x;
    for (int i = tid; i < KS * DHh; i += 256) {
        int kj = i >> 7, dd = i & 127;
        sk[kj][dd] = base[(size_t)kj * 3 * Dd + Dd + h * DHh + dd];
        sv[kj][dd] = base[(size_t)kj * 3 * Dd + 2 * Dd + h * DHh + dd];
    }
    __syncthreads();
    int w = tid >> 5, lane = tid & 31;
    const float rsDH = 0.08838834764831845f;
    for (int r = 0; r < 8; r++) {
        int qi = w * 8 + r;
        const float* qrow = base + (size_t)qi * 3 * Dd + h * DHh;
        float s0 = 0.f, s1 = 0.f;
#pragma unroll 4
        for (int dd = 0; dd < DHh; dd++) {
            float qd = qrow[dd];
            s0 = fmaf(qd, sk[lane][dd], s0);
            s1 = fmaf(qd, sk[lane + 32][dd], s1);
        }
        s0 *= rsDH; s1 *= rsDH;
        float mx = fmaxf(s0, s1);
#pragma unroll
        for (int o = 16; o > 0; o >>= 1) mx = fmaxf(mx, __shfl_xor_sync(0xffffffffu, mx, o));
        float e0 = expf(s0 - mx), e1 = expf(s1 - mx);
        float sum = e0 + e1;
#pragma unroll
        for (int o = 16; o > 0; o >>= 1) sum += __shfl_xor_sync(0xffffffffu, sum, o);
        float inv = 1.0f / sum;
        sp[qi][lane]      = e0 * inv;
        sp[qi][lane + 32] = e1 * inv;
    }
    __syncthreads();
    int d = tid & 127;
    int half = tid >> 7;
    for (int j0 = 0; j0 < 32; j0 += 4) {
        int qi = half * 32 + j0;
        float a0 = 0.f, a1 = 0.f, a2 = 0.f, a3 = 0.f;
#pragma unroll 8
        for (int kj = 0; kj < KS; kj++) {
            float vv = sv[kj][d];
            a0 = fmaf(sp[qi][kj],     vv, a0);
            a1 = fmaf(sp[qi + 1][kj], vv, a1);
            a2 = fmaf(sp[qi + 2][kj], vv, a2);
            a3 = fmaf(sp[qi + 3][kj], vv, a3);
        }
        size_t o = (size_t)b * KS * Dd + (size_t)qi * Dd + h * DHh + d;
        bf16 h0, l0;
        split1(a0, h0, l0); sah[o] = h0;          sal[o] = l0;
        split1(a1, h0, l0); sah[o + Dd] = h0;     sal[o + Dd] = l0;
        split1(a2, h0, l0); sah[o + 2 * Dd] = h0; sal[o + 2 * Dd] = l0;
        split1(a3, h0, l0); sah[o + 3 * Dd] = h0; sal[o + 3 * Dd] = l0;
    }
}

// ================= split-fp16 GEMM: fragment-pipelined, templated tiles =================
// gemmx<TB, BM, BN>: THREADS = 2*BM. Warp grid (BM/32) x 2, warp tile 32 x (BN/2).
// BK=64, 2 smem stages, 1 barrier pair per tile.
// act: 0=none, 1=gelu, 2=fused slot-softmax (TB, BM=64, BN=128 only; writes split aw).

__device__ __forceinline__ void mma_f16(float* d, const uint32_t* a, uint32_t b0, uint32_t b1) {
    asm volatile(
        "mma.sync.aligned.m16n8k16.row.col.f32.f16.f16.f32 "
        "{%0,%1,%2,%3}, {%4,%5,%6,%7}, {%8,%9}, {%0,%1,%2,%3};\n"
        : "+f"(d[0]), "+f"(d[1]), "+f"(d[2]), "+f"(d[3])
        : "r"(a[0]), "r"(a[1]), "r"(a[2]), "r"(a[3]), "r"(b0), "r"(b1));
}
__device__ __forceinline__ void cp16(bf16* s, const bf16* g) {
    uint32_t sa = (uint32_t)__cvta_generic_to_shared(s);
    asm volatile("cp.async.cg.shared.global [%0], [%1], 16;\n" :: "r"(sa), "l"(g));
}
#define LDSM4(r0, r1, r2, r3, a) \
    asm volatile("ldmatrix.sync.aligned.m8n8.x4.shared.b16 {%0,%1,%2,%3}, [%4];\n" \
                 : "=r"(r0), "=r"(r1), "=r"(r2), "=r"(r3) : "r"(a))
#define LDSM4T(r0, r1, r2, r3, a) \
    asm volatile("ldmatrix.sync.aligned.m8n8.x4.trans.shared.b16 {%0,%1,%2,%3}, [%4];\n" \
                 : "=r"(r0), "=r"(r1), "=r"(r2), "=r"(r3) : "r"(a))

template <bool TB, int BM, int BN>
__global__ void __launch_bounds__(BM * 2) gemmx(
    const bf16* __restrict__ Ah, const bf16* __restrict__ Al,
    const bf16* __restrict__ Bh, const bf16* __restrict__ Bl,
    int Kd, int ldb, long long sA, long long sB, float alpha,
    float* __restrict__ Cf, int ldc, long long sC,
    bf16* __restrict__ Ch, bf16* __restrict__ Cl, int ldch, long long sCh,
    const float* __restrict__ bias,
    const float* __restrict__ add, int ldadd, long long sAdd, int act) {
    constexpr int THREADS = BM * 2;
    constexpr int NPW = BN / 2;
    constexpr int PP  = NPW / 16;
    constexpr int NS  = NPW / 8;
    constexpr int AOFL = BM * 72;            // A-lo offset (fp16 units)
    constexpr int BOF  = 2 * BM * 72;        // B region offset
    constexpr int BROW = TB ? 72 : (BN + 8);
    constexpr int BSZH = TB ? BN * 72 : 64 * (BN + 8);
    constexpr int STG = BOF + 2 * BSZH;
    extern __shared__ __align__(16) bf16 smg[];

    int bz = blockIdx.z;
    Ah += bz * sA; Al += bz * sA;
    Bh += bz * sB; Bl += bz * sB;
    if (Cf) Cf += bz * sC;
    if (Ch) { Ch += bz * sCh; Cl += bz * sCh; }
    if (add) add += bz * sAdd;

    int bm = blockIdx.y * BM;
    int bn = blockIdx.x * BN;
    int tid = threadIdx.x, lane = tid & 31, wid = tid >> 5;
    int wm = (wid >> 1) * 32;
    int wn = (wid & 1) * NPW;
    int r = lane >> 2, cc = lane & 3;
    int arow = lane & 15, ahalf = lane >> 4;

    float acc[2][NS][4] = {};
    uint32_t ah[2][4], al[2][4], bh[NS][2], bl[NS][2];
    uint32_t base = 0;

    auto load_tile = [&](int st, int k0) {
        bf16* s = smg + st * STG;
#pragma unroll
        for (int c = tid; c < BM * 8; c += THREADS) {
            int row = c >> 3, kq = c & 7;
            cp16(s + row * 72 + kq * 8,        Ah + (size_t)(bm + row) * Kd + k0 + kq * 8);
            cp16(s + AOFL + row * 72 + kq * 8, Al + (size_t)(bm + row) * Kd + k0 + kq * 8);
        }
        if (TB) {
#pragma unroll
            for (int c = tid; c < BN * 8; c += THREADS) {
                int row = c >> 3, kq = c & 7;
                cp16(s + BOF + row * 72 + kq * 8,        Bh + (size_t)(bn + row) * ldb + k0 + kq * 8);
                cp16(s + BOF + BSZH + row * 72 + kq * 8, Bl + (size_t)(bn + row) * ldb + k0 + kq * 8);
            }
        } else {
            constexpr int CH = BN / 8;
#pragma unroll
            for (int c = tid; c < 64 * CH; c += THREADS) {
                int row = c / CH, ch = c % CH;
                cp16(s + BOF + row * BROW + ch * 8,        Bh + (size_t)(k0 + row) * ldb + bn + ch * 8);
                cp16(s + BOF + BSZH + row * BROW + ch * 8, Bl + (size_t)(k0 + row) * ldb + bn + ch * 8);
            }
        }
        asm volatile("cp.async.commit_group;\n");
    };

    auto load_frags = [&](int s) {
#pragma unroll
        for (int ms = 0; ms < 2; ms++) {
            uint32_t ad = base + ((wm + ms * 16 + arow) * 72 + s * 16 + ahalf * 8) * 2;
            LDSM4(ah[ms][0], ah[ms][1], ah[ms][2], ah[ms][3], ad);
            LDSM4(al[ms][0], al[ms][1], al[ms][2], al[ms][3], ad + AOFL * 2);
        }
        if (TB) {
#pragma unroll
            for (int pp = 0; pp < PP; pp++) {
                uint32_t bd = base + (BOF + (wn + pp * 16 + arow) * 72 + s * 16 + ahalf * 8) * 2;
                uint32_t r0, r1, r2, r3;
                LDSM4(r0, r1, r2, r3, bd);
                bh[2 * pp][0] = r0; bh[2 * pp + 1][0] = r1;
                bh[2 * pp][1] = r2; bh[2 * pp + 1][1] = r3;
                LDSM4(r0, r1, r2, r3, bd + BSZH * 2);
                bl[2 * pp][0] = r0; bl[2 * pp + 1][0] = r1;
                bl[2 * pp][1] = r2; bl[2 * pp + 1][1] = r3;
            }
        } else {
#pragma unroll
            for (int pp = 0; pp < PP; pp++) {
                uint32_t bd = base + (BOF + (s * 16 + arow) * BROW + wn + pp * 16 + ahalf * 8) * 2;
                uint32_t r0, r1, r2, r3;
                LDSM4T(r0, r1, r2, r3, bd);
                bh[2 * pp][0] = r0; bh[2 * pp][1] = r1;
                bh[2 * pp + 1][0] = r2; bh[2 * pp + 1][1] = r3;
                LDSM4T(r0, r1, r2, r3, bd + BSZH * 2);
                bl[2 * pp][0] = r0; bl[2 * pp][1] = r1;
                bl[2 * pp + 1][0] = r2; bl[2 * pp + 1][1] = r3;
            }
        }
    };

    auto mma_all = [&]() {
#pragma unroll
        for (int ns = 0; ns < NS; ns++)
#pragma unroll
            for (int ms = 0; ms < 2; ms++)
                mma_f16(acc[ms][ns], ah[ms], bh[ns][0], bh[ns][1]);
#pragma unroll
        for (int ns = 0; ns < NS; ns++)
#pragma unroll
            for (int ms = 0; ms < 2; ms++)
                mma_f16(acc[ms][ns], ah[ms], bl[ns][0], bl[ns][1]);
#pragma unroll
        for (int ns = 0; ns < NS; ns++)
#pragma unroll
            for (int ms = 0; ms < 2; ms++)
                mma_f16(acc[ms][ns], al[ms], bh[ns][0], bh[ns][1]);
    };

    int T = Kd / 64;
    load_tile(0, 0);
    uint32_t smem_base = (uint32_t)__cvta_generic_to_shared(smg);

    for (int t = 0; t < T; t++) {
        asm volatile("cp.async.wait_group 0;\n");
        __syncthreads();
        if (t + 1 < T) load_tile((t + 1) & 1, (t + 1) * 64);
        base = smem_base + (t & 1) * STG * 2;
#pragma unroll
        for (int s = 0; s < 4; s++) {
            load_frags(s);
            mma_all();
        }
        __syncthreads();
    }

    // ---- fused slot-softmax epilogue (attn only) ----
    bool done = false;
    if constexpr (TB && BM == 64 && BN == 128) {
        if (act == 2) {
            float* sc = (float*)smg;   // 64 x 128 fp32 scratch (32 KB <= pipeline smem)
            __syncthreads();
#pragma unroll
            for (int ms = 0; ms < 2; ms++) {
#pragma unroll
                for (int ns = 0; ns < NS; ns++) {
                    int rr = wm + ms * 16 + r;
                    int jl = wn + ns * 8 + 2 * cc;
                    sc[rr * 128 + jl]           = acc[ms][ns][0] * alpha;
                    sc[rr * 128 + jl + 1]       = acc[ms][ns][1] * alpha;
                    sc[(rr + 8) * 128 + jl]     = acc[ms][ns][2] * alpha;
                    sc[(rr + 8) * 128 + jl + 1] = acc[ms][ns][3] * alpha;
                }
            }
            __syncthreads();
            int j = tid;   // 128 threads, one token column each
            float m = -1e30f;
#pragma unroll 8
            for (int k = 0; k < KS; k++) m = fmaxf(m, sc[k * 128 + j]);
            float ssum = 0.f;
#pragma unroll 8
            for (int k = 0; k < KS; k++) ssum += expf(sc[k * 128 + j] - m);
            float inv = 1.0f / ssum;
#pragma unroll 8
            for (int k = 0; k < KS; k++) {
                float e = expf(sc[k * 128 + j] - m) * inv;
                bf16 hh, ll;
                split1(e, hh, ll);
                Ch[(size_t)k * ldch + bn + j] = hh;
                Cl[(size_t)k * ldch + bn + j] = ll;
            }
            done = true;
        }
    }

    if (!done) {
#pragma unroll
        for (int ms = 0; ms < 2; ms++) {
            int i0 = bm + wm + ms * 16 + r;
#pragma unroll
            for (int ns = 0; ns < NS; ns++) {
                int j = bn + wn + ns * 8 + 2 * cc;
                float v00 = acc[ms][ns][0] * alpha, v01 = acc[ms][ns][1] * alpha;
                float v10 = acc[ms][ns][2] * alpha, v11 = acc[ms][ns][3] * alpha;
                if (bias) {
                    float bj0 = bias[j], bj1 = bias[j + 1];
                    v00 += bj0; v01 += bj1; v10 += bj0; v11 += bj1;
                }
                if (act == 1) {
                    v00 = gelu_exact(v00); v01 = gelu_exact(v01);
                    v10 = gelu_exact(v10); v11 = gelu_exact(v11);
                }
                if (add) {
                    v00 += add[(size_t)i0 * ldadd + j];
                    v01 += add[(size_t)i0 * ldadd + j + 1];
                    v10 += add[(size_t)(i0 + 8) * ldadd + j];
                    v11 += add[(size_t)(i0 + 8) * ldadd + j + 1];
                }
                if (Cf) {
                    float2 a2; a2.x = v00; a2.y = v01;
                    float2 b2; b2.x = v10; b2.y = v11;
                    *(float2*)(Cf + (size_t)i0 * ldc + j) = a2;
                    *(float2*)(Cf + (size_t)(i0 + 8) * ldc + j) = b2;
                }
                if (Ch) {
                    bf16 h00, l00, h01, l01, h10, l10, h11, l11;
                    split1(v00, h00, l00); split1(v01, h01, l01);
                    split1(v10, h10, l10); split1(v11, h11, l11);
                    *(bf162*)(Ch + (size_t)i0 * ldch + j) = mk2(h00, h01);
                    *(bf162*)(Cl + (size_t)i0 * ldch + j) = mk2(l00, l01);
                    *(bf162*)(Ch + (size_t)(i0 + 8) * ldch + j) = mk2(h10, h11);
                    *(bf162*)(Cl + (size_t)(i0 + 8) * ldch + j) = mk2(l10, l11);
                }
            }
        }
    }
}

// ---------------- launcher ----------------
#define SYM(p, s) cudaGetSymbolAddress((void**)&p, s)

extern "C" void kernel_launch(void* const* d_in, const int* in_sizes, int n_in,
                              void* d_out, int out_size) {
    const float* vis       = (const float*)d_in[0];
    const float* slot_init = (const float*)d_in[1];
    const float* ln_vis_g  = (const float*)d_in[2];
    const float* ln_vis_b  = (const float*)d_in[3];
    const float* ln_sl_g   = (const float*)d_in[4];
    const float* ln_sl_b   = (const float*)d_in[5];
    const float* Wq        = (const float*)d_in[6];
    const float* Wk        = (const float*)d_in[7];
    const float* Wv        = (const float*)d_in[8];
    const float* Wo        = (const float*)d_in[9];
    const float* mha_in_w  = (const float*)d_in[10];
    const float* mha_in_b  = (const float*)d_in[11];
    const float* mha_out_w = (const float*)d_in[12];
    const float* mha_out_b = (const float*)d_in[13];
    const float* ln_sa_g   = (const float*)d_in[14];
    const float* ln_sa_b   = (const float*)d_in[15];
    const float* ln_ffn_g  = (const float*)d_in[16];
    const float* ln_ffn_b  = (const float*)d_in[17];
    const float* W1        = (const float*)d_in[18];
    const float* b1        = (const float*)d_in[19];
    const float* W2        = (const float*)d_in[20];
    const float* b2        = (const float*)d_in[21];

    bf16 *vnh, *vnl, *Wkh, *Wkl, *Wqh, *Wql, *Wvh, *Wvl, *Woh, *Wol;
    bf16 *Wqkh, *Wqkl, *Wvoh, *Wvol, *miwh, *miwl, *mowh, *mowl;
    bf16 *W1h, *W1l, *W2h, *W2l, *snh, *snl, *qh, *ql, *awh, *awl;
    bf16 *u1h, *u1l, *slbh, *slbl, *sah, *sal, *hh, *hl, *tbh, *tbl;
    float *slots, *qkv, *tmp;
    SYM(vnh, g_vnh); SYM(vnl, g_vnl);
    SYM(Wkh, g_Wkh); SYM(Wkl, g_Wkl); SYM(Wqh, g_Wqh); SYM(Wql, g_Wql);
    SYM(Wvh, g_Wvh); SYM(Wvl, g_Wvl); SYM(Woh, g_Woh); SYM(Wol, g_Wol);
    SYM(Wqkh, g_Wqkh); SYM(Wqkl, g_Wqkl); SYM(Wvoh, g_Wvoh); SYM(Wvol, g_Wvol);
    SYM(miwh, g_miwh); SYM(miwl, g_miwl); SYM(mowh, g_mowh); SYM(mowl, g_mowl);
    SYM(W1h, g_W1h); SYM(W1l, g_W1l); SYM(W2h, g_W2h); SYM(W2l, g_W2l);
    SYM(snh, g_snh); SYM(snl, g_snl); SYM(qh, g_qh); SYM(ql, g_ql);
    SYM(awh, g_awh); SYM(awl, g_awl); SYM(u1h, g_u1h); SYM(u1l, g_u1l);
    SYM(slbh, g_slbh); SYM(slbl, g_slbl); SYM(sah, g_sah); SYM(sal, g_sal);
    SYM(hh, g_hh); SYM(hl, g_hl); SYM(tbh, g_tbh); SYM(tbl, g_tbl);
    SYM(slots, g_slots); SYM(qkv, g_qkv); SYM(tmp, g_tmp);

    float* out = (float*)d_out;

    const int SM_128_64  = (2 * 128 * 72 + 2 * 64 * 72) * 2 * 2;    // 110592
    const int SM_64_128T = (2 * 64 * 72 + 2 * 128 * 72) * 2 * 2;    // 110592
    const int SM_64_64N  = (2 * 64 * 72 + 2 * 64 * 72) * 2 * 2;     // 73728
    const int SM_MHA     = 33024 + 32768 + 16384;                   // 82176
    cudaFuncSetAttribute(gemmx<true, 128, 64>,  cudaFuncAttributeMaxDynamicSharedMemorySize, SM_128_64);
    cudaFuncSetAttribute(gemmx<false, 128, 64>, cudaFuncAttributeMaxDynamicSharedMemorySize, SM_128_64);
    cudaFuncSetAttribute(gemmx<true, 64, 128>,  cudaFuncAttributeMaxDynamicSharedMemorySize, SM_64_128T);
    cudaFuncSetAttribute(gemmx<false, 64, 64>,  cudaFuncAttributeMaxDynamicSharedMemorySize, SM_64_64N);
    cudaFuncSetAttribute(mha_fused, cudaFuncAttributeMaxDynamicSharedMemorySize, SM_MHA);

    // ---- merged weight split ----
    {
        SJ j;
        j.s[0] = Wq;  j.h[0] = Wqh;  j.l[0] = Wql;
        j.s[1] = Wk;  j.h[1] = Wkh;  j.l[1] = Wkl;
        j.s[2] = Wv;  j.h[2] = Wvh;  j.l[2] = Wvl;
        j.s[3] = Wo;  j.h[3] = Woh;  j.l[3] = Wol;
        j.s[4] = mha_out_w; j.h[4] = mowh; j.l[4] = mowl;
        j.s[5] = mha_in_w;  j.h[5] = miwh; j.l[5] = miwl;
        j.s[6] = W1;  j.h[6] = W1h;  j.l[6] = W1l;
        j.s[7] = W2;  j.h[7] = W2h;  j.l[7] = W2l;
        int blocks[8] = {1024, 1024, 1024, 1024, 1024, 3072, 2048, 2048};
        j.cum[0] = 0;
        for (int i = 0; i < 8; i++) j.cum[i + 1] = j.cum[i] + blocks[i];
        split_all<<<j.cum[8], 256>>>(j);
    }

    // vn = LN(visual_tokens) -> split fp16
    ln_kernel<<<Bb * Nn, 256>>>(vis, nullptr, ln_vis_g, ln_vis_b, nullptr, vnh, vnl);

    // Wqk = Wq @ Wk^T (NT); Wvo = Wv @ Wo (NN)
    gemmx<true, 128, 64><<<dim3(16, 8, 1), 256, SM_128_64>>>(Wqh, Wql, Wkh, Wkl, Dd, Dd, 0, 0, 1.0f,
        nullptr, 0, 0, Wqkh, Wqkl, Dd, 0, nullptr, nullptr, 0, 0, 0);
    gemmx<false, 128, 64><<<dim3(16, 8, 1), 256, SM_128_64>>>(Wvh, Wvl, Woh, Wol, Dd, Dd, 0, 0, 1.0f,
        nullptr, 0, 0, Wvoh, Wvol, Dd, 0, nullptr, nullptr, 0, 0, 0);

    bcast_slots<<<(Bb * KS * Dd) / 256, 256>>>(slot_init, slots);

    const int Mfull = Bb * KS;  // 1024
    for (int it = 0; it < 2; it++) {
        ln_kernel<<<Mfull, 256>>>(slots, nullptr, ln_sl_g, ln_sl_b, nullptr, snh, snl);
        // q = sn @ Wqk  (NN)
        gemmx<false, 128, 64><<<dim3(16, 8, 1), 256, SM_128_64>>>(snh, snl, Wqkh, Wqkl, Dd, Dd, 0, 0, 1.0f,
            nullptr, 0, 0, qh, ql, Dd, 0, nullptr, nullptr, 0, 0, 0);
        // aw = softmax_slots((1/32) q[b] @ vn[b]^T)  -- fused epilogue, writes split aw
        gemmx<true, 64, 128><<<dim3(32, 1, Bb), 128, SM_64_128T>>>(qh, ql, vnh, vnl, Dd, Dd,
            (long long)KS * Dd, (long long)Nn * Dd, 0.03125f,
            nullptr, 0, 0, awh, awl, Nn, (long long)KS * Nn,
            nullptr, nullptr, 0, 0, 2);
        // u1[b] = aw[b] @ vn[b]  (NN, M=64, K=4096)
        gemmx<false, 64, 64><<<dim3(16, 1, Bb), 128, SM_64_64N>>>(awh, awl, vnh, vnl, Nn, Dd,
            (long long)KS * Nn, (long long)Nn * Dd, 1.0f,
            nullptr, 0, 0, u1h, u1l, Dd, (long long)KS * Dd,
            nullptr, nullptr, 0, 0, 0);
        // slots = slots + u1 @ Wvo  (NN)
        gemmx<false, 128, 64><<<dim3(16, 8, 1), 256, SM_128_64>>>(u1h, u1l, Wvoh, Wvol, Dd, Dd, 0, 0, 1.0f,
            slots, Dd, 0, slbh, slbl, Dd, 0, nullptr, slots, Dd, 0, 0);
        // qkv = slots @ mha_in_w^T + b  (NT, N=3072)
        gemmx<true, 128, 64><<<dim3(48, 8, 1), 256, SM_128_64>>>(slbh, slbl, miwh, miwl, Dd, Dd, 0, 0, 1.0f,
            qkv, 3 * Dd, 0, nullptr, nullptr, 0, 0, mha_in_b, nullptr, 0, 0, 0);
        // fused per-head attention
        mha_fused<<<Bb * Hh, 256, SM_MHA>>>(qkv, sah, sal);
        // tmp = sa @ mha_out_w^T + b  (NT)
        gemmx<true, 128, 64><<<dim3(16, 8, 1), 256, SM_128_64>>>(sah, sal, mowh, mowl, Dd, Dd, 0, 0, 1.0f,
            tmp, Dd, 0, nullptr, nullptr, 0, 0, mha_out_b, nullptr, 0, 0, 0);
        ln_kernel<<<Mfull, 256>>>(slots, tmp, ln_sa_g, ln_sa_b, slots, nullptr, nullptr);
    }

    ln_kernel<<<Mfull, 256>>>(slots, nullptr, ln_ffn_g, ln_ffn_b, nullptr, hh, hl);
    // tb = gelu(h @ W1 + b1)  (NN, N=2048)
    gemmx<false, 128, 64><<<dim3(32, 8, 1), 256, SM_128_64>>>(hh, hl, W1h, W1l, Dd, 2 * Dd, 0, 0, 1.0f,
        nullptr, 0, 0, tbh, tbl, 2 * Dd, 0, b1, nullptr, 0, 0, 1);
    // out = slots + tb @ W2 + b2  (NN, K=2048)
    gemmx<false, 128, 64><<<dim3(16, 8, 1), 256, SM_128_64>>>(tbh, tbl, W2h, W2l, 2 * Dd, Dd, 0, 0, 1.0f,
        out, Dd, 0, nullptr, nullptr, 0, 0, b2, slots, Dd, 0, 0);
}